// round 8
// baseline (speedup 1.0000x reference)
#include <cuda_runtime.h>
#include <cuda_fp16.h>
#include <cuda_fp8.h>
#include <cstdint>

#define M_DIM 16384
#define N_DIM 1000
#define N_PAD 1024
#define K_DIM 2048
#define BM 128
#define BN 128
#define BK 128             // fp8 elems per stage = 128 B/row (SW128 atom)
#define NKT (K_DIM / BK)   // 16 k-tiles
#define NSTAGE 3
#define STG_STRIDE 32768u  // A 16KB + B 16KB per stage
#define EPS_D2 1e-12f

// ---- scratch (allocation-free: __device__ globals) ----
__device__ __align__(256) uint8_t g_x8[(size_t)M_DIM * K_DIM];
__device__ __align__(256) uint8_t g_w8[(size_t)N_PAD * K_DIM];
__device__ float g_x2[M_DIM];
__device__ float g_w2[N_PAD];

// ---------------- helpers ----------------
__device__ __forceinline__ void cp_async16(uint32_t smem, const void* gmem) {
    asm volatile("cp.async.cg.shared.global [%0], [%1], 16;\n" :: "r"(smem), "l"(gmem));
}
__device__ __forceinline__ void cp_commit() {
    asm volatile("cp.async.commit_group;\n");
}
template <int Nrem>
__device__ __forceinline__ void cp_wait() {
    asm volatile("cp.async.wait_group %0;\n" :: "n"(Nrem));
}
__device__ __forceinline__ void ldsm_x4(uint32_t& r0, uint32_t& r1, uint32_t& r2, uint32_t& r3,
                                        uint32_t addr) {
    asm volatile("ldmatrix.sync.aligned.m8n8.x4.shared.b16 {%0,%1,%2,%3}, [%4];\n"
                 : "=r"(r0), "=r"(r1), "=r"(r2), "=r"(r3) : "r"(addr));
}
// fp8 e4m3 MMA, k32, f32 accumulate
__device__ __forceinline__ void mma16832_fp8(float* c,
                                             uint32_t a0, uint32_t a1, uint32_t a2, uint32_t a3,
                                             uint32_t b0, uint32_t b1) {
    asm volatile("mma.sync.aligned.m16n8k32.row.col.f32.e4m3.e4m3.f32 "
                 "{%0,%1,%2,%3}, {%4,%5,%6,%7}, {%8,%9}, {%0,%1,%2,%3};\n"
                 : "+f"(c[0]), "+f"(c[1]), "+f"(c[2]), "+f"(c[3])
                 : "r"(a0), "r"(a1), "r"(a2), "r"(a3), "r"(b0), "r"(b1));
}

__device__ __forceinline__ uint32_t pack4_e4m3(float4 v) {
    const uint16_t lo = __nv_cvt_float2_to_fp8x2(make_float2(v.x, v.y),
                                                 __NV_SATFINITE, __NV_E4M3);
    const uint16_t hi = __nv_cvt_float2_to_fp8x2(make_float2(v.z, v.w),
                                                 __NV_SATFINITE, __NV_E4M3);
    return (uint32_t)lo | ((uint32_t)hi << 16);
}

// ---------------- conversion kernels (warp-per-row, MLP=16) ----------------
__global__ void convert_x_kernel(const float* __restrict__ src) {
    const int row  = blockIdx.x * 8 + (threadIdx.x >> 5);
    const int lane = threadIdx.x & 31;
    const float4* sr = reinterpret_cast<const float4*>(src + (size_t)row * K_DIM);
    uint32_t* dr = reinterpret_cast<uint32_t*>(g_x8 + (size_t)row * K_DIM);
    float s = 0.f;
    #pragma unroll
    for (int i = 0; i < 16; ++i) {           // 512 float4 / 32 lanes
        const int idx = lane + (i << 5);
        float4 v = sr[idx];
        s += v.x * v.x + v.y * v.y + v.z * v.z + v.w * v.w;
        dr[idx] = pack4_e4m3(v);
    }
    #pragma unroll
    for (int o = 16; o > 0; o >>= 1) s += __shfl_xor_sync(0xffffffffu, s, o);
    if (lane == 0) g_x2[row] = s;
}

__global__ void convert_w_kernel(const float* __restrict__ src) {
    const int row  = blockIdx.x * 8 + (threadIdx.x >> 5);
    const int lane = threadIdx.x & 31;
    uint32_t* dr = reinterpret_cast<uint32_t*>(g_w8 + (size_t)row * K_DIM);
    float s = 0.f;
    if (row < N_DIM) {
        const float4* sr = reinterpret_cast<const float4*>(src + (size_t)row * K_DIM);
        #pragma unroll
        for (int i = 0; i < 16; ++i) {
            const int idx = lane + (i << 5);
            float4 v = sr[idx];
            s += v.x * v.x + v.y * v.y + v.z * v.z + v.w * v.w;
            dr[idx] = pack4_e4m3(v);
        }
    } else {
        #pragma unroll
        for (int i = 0; i < 16; ++i) dr[lane + (i << 5)] = 0u;
    }
    #pragma unroll
    for (int o = 16; o > 0; o >>= 1) s += __shfl_xor_sync(0xffffffffu, s, o);
    if (lane == 0) g_w2[row] = s;
}

// ---------------- GEMM + fused distance epilogue (FP8) ----------------
// CTA tile 128x128x128(fp8), 8 warps (2M x 4N), warp tile 64x32.
// Row = 128 B = 8 chunks of 16B; swizzle chunk' = chunk ^ (row & 7).
// 3-stage cp.async pipeline, single barrier/iter, b-frag double buffer.
// 96KB smem, 2 CTAs/SM. mma m16n8k32 e4m3, f32 accumulate.

__device__ __forceinline__ void load_stage(uint32_t sbase, int buf, int bm, int bn,
                                           int kt, int tid) {
    const int k0 = kt * BK;
    const uint32_t sA = sbase + (uint32_t)buf * STG_STRIDE;
    const uint32_t sB = sA + 16384u;
    #pragma unroll
    for (int i = 0; i < 4; ++i) {            // 128 rows x 8 chunks / 256 thr
        int ch = tid + (i << 8);
        int r = ch >> 3, c = ch & 7;
        cp_async16(sA + (uint32_t)(((r << 3) | (c ^ (r & 7))) << 4),
                   g_x8 + (size_t)(bm + r) * K_DIM + k0 + (c << 4));
    }
    #pragma unroll
    for (int i = 0; i < 4; ++i) {
        int ch = tid + (i << 8);
        int r = ch >> 3, c = ch & 7;
        cp_async16(sB + (uint32_t)(((r << 3) | (c ^ (r & 7))) << 4),
                   g_w8 + (size_t)(bn + r) * K_DIM + k0 + (c << 4));
    }
    cp_commit();
}

__device__ __forceinline__ void load_b_frags(uint32_t b[2][4], uint32_t sB, int kk,
                                             int lane, int wn) {
    #pragma unroll
    for (int nb = 0; nb < 2; ++nb) {
        int r = wn * 32 + nb * 16 + (lane & 7) + ((lane & 16) >> 1);
        int c = kk * 2 + ((lane >> 3) & 1);
        ldsm_x4(b[nb][0], b[nb][1], b[nb][2], b[nb][3],
                sB + (uint32_t)(((r << 3) | (c ^ (r & 7))) << 4));
    }
}

__global__ void __launch_bounds__(256, 2)
gemm_dist_kernel(const float* __restrict__ scales, float* __restrict__ out) {
    extern __shared__ __align__(128) char smem[];
    const uint32_t sbase = (uint32_t)__cvta_generic_to_shared(smem);

    const int tid  = threadIdx.x;
    const int lane = tid & 31;
    const int wid  = tid >> 5;
    const int wm   = wid & 1;   // 0..1 -> 64 rows each
    const int wn   = wid >> 1;  // 0..3 -> 32 cols each
    const int bm   = blockIdx.y * BM;
    const int bn   = blockIdx.x * BN;

    float acc[4][4][4];
    #pragma unroll
    for (int i = 0; i < 4; ++i)
        #pragma unroll
        for (int j = 0; j < 4; ++j)
            #pragma unroll
            for (int k = 0; k < 4; ++k) acc[i][j][k] = 0.f;

    uint32_t a[4][4];      // A fragments (4 m-tiles, k32 each)
    uint32_t b[2][2][4];   // double-buffered B fragments

    load_stage(sbase, 0, bm, bn, 0, tid);
    load_stage(sbase, 1, bm, bn, 1, tid);

    #pragma unroll 1
    for (int kt = 0; kt < NKT; ++kt) {
        const int buf = kt % NSTAGE;
        cp_wait<1>();
        __syncthreads();   // single barrier per iteration

        // buffer (kt+2)%3 last read in iter kt-1; barrier above protects it.
        if (kt + 2 < NKT) load_stage(sbase, (kt + 2) % NSTAGE, bm, bn, kt + 2, tid);
        else              cp_commit();  // keep group count aligned for cp_wait<1>

        const uint32_t sA = sbase + (uint32_t)buf * STG_STRIDE;
        const uint32_t sB = sA + 16384u;

        load_b_frags(b[0], sB, 0, lane, wn);

        #pragma unroll
        for (int kk = 0; kk < 4; ++kk) {   // 4 x k32 per BK=128
            const int cur = kk & 1;
            // A fragments for this kk (TLP-hidden at 16 warps/SM)
            #pragma unroll
            for (int mt = 0; mt < 4; ++mt) {
                int r = wm * 64 + mt * 16 + (lane & 15);
                int c = kk * 2 + (lane >> 4);
                ldsm_x4(a[mt][0], a[mt][1], a[mt][2], a[mt][3],
                        sA + (uint32_t)(((r << 3) | (c ^ (r & 7))) << 4));
            }
            if (kk < 3) load_b_frags(b[cur ^ 1], sB, kk + 1, lane, wn);

            #pragma unroll
            for (int mt = 0; mt < 4; ++mt)
                #pragma unroll
                for (int nt = 0; nt < 4; ++nt)
                    mma16832_fp8(acc[mt][nt],
                                 a[mt][0], a[mt][1], a[mt][2], a[mt][3],
                                 b[cur][nt >> 1][(nt & 1) * 2],
                                 b[cur][nt >> 1][(nt & 1) * 2 + 1]);
        }
    }

    // Epilogue: out = -s * sqrt(max(x2 + w2 - 2*cross, eps))
    const float sc = __ldg(scales);
    #pragma unroll
    for (int mt = 0; mt < 4; ++mt) {
        const int row = bm + wm * 64 + mt * 16 + (lane >> 2);
        const float x2a = g_x2[row];
        const float x2b = g_x2[row + 8];
        #pragma unroll
        for (int nt = 0; nt < 4; ++nt) {
            const int col = bn + wn * 32 + nt * 8 + ((lane & 3) << 1);
            if (col < N_DIM) {   // col even, N_DIM even -> col+1 also valid
                const float w2a = g_w2[col];
                const float w2b = g_w2[col + 1];
                float2 v;
                v.x = -sc * sqrtf(fmaxf(x2a + w2a - 2.f * acc[mt][nt][0], EPS_D2));
                v.y = -sc * sqrtf(fmaxf(x2a + w2b - 2.f * acc[mt][nt][1], EPS_D2));
                *reinterpret_cast<float2*>(out + (size_t)row * N_DIM + col) = v;
                v.x = -sc * sqrtf(fmaxf(x2b + w2a - 2.f * acc[mt][nt][2], EPS_D2));
                v.y = -sc * sqrtf(fmaxf(x2b + w2b - 2.f * acc[mt][nt][3], EPS_D2));
                *reinterpret_cast<float2*>(out + (size_t)(row + 8) * N_DIM + col) = v;
            }
        }
    }
}

// ---------------- launch ----------------
extern "C" void kernel_launch(void* const* d_in, const int* in_sizes, int n_in,
                              void* d_out, int out_size) {
    const float* x      = (const float*)d_in[0];  // [16384, 2048]
    const float* w      = (const float*)d_in[1];  // [1000, 2048]
    const float* scales = (const float*)d_in[2];  // [1]
    float* out          = (float*)d_out;          // [16384, 1000]

    convert_x_kernel<<<M_DIM / 8, 256>>>(x);
    convert_w_kernel<<<N_PAD / 8, 256>>>(w);

    cudaFuncSetAttribute(gemm_dist_kernel,
                         cudaFuncAttributeMaxDynamicSharedMemorySize, NSTAGE * STG_STRIDE);
    dim3 grid(N_PAD / BN, M_DIM / BM);  // (8, 128) = 1024 CTAs
    gemm_dist_kernel<<<grid, 256, NSTAGE * STG_STRIDE>>>(scales, out);
}

// round 10
// speedup vs baseline: 1.1632x; 1.1632x over previous
#include <cuda_runtime.h>
#include <cuda_bf16.h>
#include <cstdint>

#define M_DIM 16384
#define N_DIM 1000
#define N_PAD 1024
#define K_DIM 2048
#define BM 128
#define BN 128
#define BK 64
#define NKT (K_DIM / BK)   // 32 k-tiles
#define NSTAGE 3
#define STG_STRIDE 32768u  // A 16KB + B 16KB per stage
#define EPS_D2 1e-12f
#define NCHUNK 4
#define CHUNK_ROWS (M_DIM / NCHUNK)   // 4096
#define NCONV 64                       // producer CTAs (first in grid order)
#define NGEMM ((M_DIM / BM) * (N_PAD / BN))  // 1024

// ---- scratch (allocation-free: __device__ globals) ----
__device__ __align__(256) __nv_bfloat16 g_xb[(size_t)M_DIM * K_DIM];
__device__ __align__(256) __nv_bfloat16 g_wb[(size_t)N_PAD * K_DIM];
__device__ float g_x2[M_DIM];
__device__ float g_w2[N_PAD];
__device__ int g_cnt[NCHUNK];
__device__ int g_flag[NCHUNK];

// ---------------- helpers ----------------
__device__ __forceinline__ void cp_async16(uint32_t smem, const void* gmem) {
    asm volatile("cp.async.cg.shared.global [%0], [%1], 16;\n" :: "r"(smem), "l"(gmem));
}
__device__ __forceinline__ void cp_commit() {
    asm volatile("cp.async.commit_group;\n");
}
template <int Nrem>
__device__ __forceinline__ void cp_wait() {
    asm volatile("cp.async.wait_group %0;\n" :: "n"(Nrem));
}
__device__ __forceinline__ void ldsm_x4(uint32_t& r0, uint32_t& r1, uint32_t& r2, uint32_t& r3,
                                        uint32_t addr) {
    asm volatile("ldmatrix.sync.aligned.m8n8.x4.shared.b16 {%0,%1,%2,%3}, [%4];\n"
                 : "=r"(r0), "=r"(r1), "=r"(r2), "=r"(r3) : "r"(addr));
}
__device__ __forceinline__ void mma16816(float* c,
                                         uint32_t a0, uint32_t a1, uint32_t a2, uint32_t a3,
                                         uint32_t b0, uint32_t b1) {
    asm volatile("mma.sync.aligned.m16n8k16.row.col.f32.bf16.bf16.f32 "
                 "{%0,%1,%2,%3}, {%4,%5,%6,%7}, {%8,%9}, {%0,%1,%2,%3};\n"
                 : "+f"(c[0]), "+f"(c[1]), "+f"(c[2]), "+f"(c[3])
                 : "r"(a0), "r"(a1), "r"(a2), "r"(a3), "r"(b0), "r"(b1));
}

// ---------------- flag reset (runs first, same stream) ----------------
__global__ void reset_kernel() {
    if (threadIdx.x < NCHUNK) { g_cnt[threadIdx.x] = 0; g_flag[threadIdx.x] = 0; }
}

// ---------------- per-row converters (warp-collective, MLP=16) ----------------
__device__ __forceinline__ void conv_row_x(const float* __restrict__ src, int row, int lane) {
    const float4* sr = reinterpret_cast<const float4*>(src + (size_t)row * K_DIM);
    __nv_bfloat162* dr = reinterpret_cast<__nv_bfloat162*>(g_xb + (size_t)row * K_DIM);
    float s = 0.f;
    #pragma unroll
    for (int i = 0; i < 16; ++i) {
        const int idx = lane + (i << 5);
        float4 v = sr[idx];
        s += v.x * v.x + v.y * v.y + v.z * v.z + v.w * v.w;
        dr[2 * idx]     = __floats2bfloat162_rn(v.x, v.y);
        dr[2 * idx + 1] = __floats2bfloat162_rn(v.z, v.w);
    }
    #pragma unroll
    for (int o = 16; o > 0; o >>= 1) s += __shfl_xor_sync(0xffffffffu, s, o);
    if (lane == 0) g_x2[row] = s;
}
__device__ __forceinline__ void conv_row_w(const float* __restrict__ src, int row, int lane) {
    __nv_bfloat162* dr = reinterpret_cast<__nv_bfloat162*>(g_wb + (size_t)row * K_DIM);
    float s = 0.f;
    if (row < N_DIM) {
        const float4* sr = reinterpret_cast<const float4*>(src + (size_t)row * K_DIM);
        #pragma unroll
        for (int i = 0; i < 16; ++i) {
            const int idx = lane + (i << 5);
            float4 v = sr[idx];
            s += v.x * v.x + v.y * v.y + v.z * v.z + v.w * v.w;
            dr[2 * idx]     = __floats2bfloat162_rn(v.x, v.y);
            dr[2 * idx + 1] = __floats2bfloat162_rn(v.z, v.w);
        }
    } else {
        const __nv_bfloat162 z = __floats2bfloat162_rn(0.f, 0.f);
        #pragma unroll
        for (int i = 0; i < 16; ++i) {
            const int idx = lane + (i << 5);
            dr[2 * idx] = z; dr[2 * idx + 1] = z;
        }
    }
    #pragma unroll
    for (int o = 16; o > 0; o >>= 1) s += __shfl_xor_sync(0xffffffffu, s, o);
    if (lane == 0) g_w2[row] = s;
}

// ---------------- GEMM helpers (R5 config, unchanged) ----------------
__device__ __forceinline__ void load_stage(uint32_t sbase, int buf, int bm, int bn,
                                           int kt, int tid) {
    const int k0 = kt * BK;
    const uint32_t sA = sbase + (uint32_t)buf * STG_STRIDE;
    const uint32_t sB = sA + 16384u;
    #pragma unroll
    for (int i = 0; i < 4; ++i) {
        int ch = tid + (i << 8);
        int r = ch >> 3, c = ch & 7;
        cp_async16(sA + (uint32_t)(((r << 3) | (c ^ (r & 7))) << 4),
                   g_xb + (size_t)(bm + r) * K_DIM + k0 + (c << 3));
    }
    #pragma unroll
    for (int i = 0; i < 4; ++i) {
        int ch = tid + (i << 8);
        int r = ch >> 3, c = ch & 7;
        cp_async16(sB + (uint32_t)(((r << 3) | (c ^ (r & 7))) << 4),
                   g_wb + (size_t)(bn + r) * K_DIM + k0 + (c << 3));
    }
    cp_commit();
}

__device__ __forceinline__ void load_b_frags(uint32_t b[2][4], uint32_t sB, int kk,
                                             int lane, int wn) {
    #pragma unroll
    for (int nb = 0; nb < 2; ++nb) {
        int r = wn * 32 + nb * 16 + (lane & 7) + ((lane & 16) >> 1);
        int c = kk * 2 + ((lane >> 3) & 1);
        ldsm_x4(b[nb][0], b[nb][1], b[nb][2], b[nb][3],
                sB + (uint32_t)(((r << 3) | (c ^ (r & 7))) << 4));
    }
}

// ---------------- fused kernel: 64 producer CTAs + 1024 GEMM CTAs ----------------
__global__ void __launch_bounds__(256, 2)
fused_kernel(const float* __restrict__ x, const float* __restrict__ w,
             const float* __restrict__ scales, float* __restrict__ out) {
    const int bid  = blockIdx.x;
    const int tid  = threadIdx.x;
    const int lane = tid & 31;
    const int wid  = tid >> 5;

    if (bid < NCONV) {
        // ======== producer role: convert w, then x chunk by chunk ========
        // w: 128 groups of 8 rows; each CTA's 8 warps take one row per group
        for (int g = bid; g < N_PAD / 8; g += NCONV)
            conv_row_w(w, g * 8 + wid, lane);
        // x: 4 chunks x 512 groups
        for (int c = 0; c < NCHUNK; ++c) {
            for (int g = bid; g < CHUNK_ROWS / 8; g += NCONV)
                conv_row_x(x, c * CHUNK_ROWS + g * 8 + wid, lane);
            __syncthreads();
            if (tid == 0) {
                __threadfence();   // make converted data + norms visible (release)
                if (atomicAdd(&g_cnt[c], 1) == NCONV - 1)
                    atomicExch(&g_flag[c], 1);
            }
        }
        return;
    }

    // ======== GEMM role (R5 config) ========
    extern __shared__ __align__(128) char smem[];
    const uint32_t sbase = (uint32_t)__cvta_generic_to_shared(smem);

    const int gid = bid - NCONV;
    const int bm  = (gid >> 3) * BM;
    const int bn  = (gid & 7) * BN;
    const int wm  = wid & 1;   // 0..1 -> 64 rows each
    const int wn  = wid >> 1;  // 0..3 -> 32 cols each

    // wait for this M-chunk's data (flag[c] implies w + chunks 0..c converted)
    if (tid == 0) {
        const int c = gid >> 8;   // 256 GEMM CTAs per chunk
        unsigned f;
        do {
            asm volatile("ld.acquire.gpu.global.u32 %0, [%1];"
                         : "=r"(f) : "l"(&g_flag[c]) : "memory");
            if (f == 0) __nanosleep(128);
        } while (f == 0);
    }
    __syncthreads();

    float acc[4][4][4];
    #pragma unroll
    for (int i = 0; i < 4; ++i)
        #pragma unroll
        for (int j = 0; j < 4; ++j)
            #pragma unroll
            for (int k = 0; k < 4; ++k) acc[i][j][k] = 0.f;

    uint32_t a[4][4];      // single-buffered A fragments
    uint32_t b[2][2][4];   // double-buffered B fragments

    load_stage(sbase, 0, bm, bn, 0, tid);
    load_stage(sbase, 1, bm, bn, 1, tid);

    #pragma unroll 1
    for (int kt = 0; kt < NKT; ++kt) {
        const int buf = kt % NSTAGE;
        cp_wait<1>();
        __syncthreads();   // single barrier per iteration

        if (kt + 2 < NKT) load_stage(sbase, (kt + 2) % NSTAGE, bm, bn, kt + 2, tid);
        else              cp_commit();  // keep group count aligned for cp_wait<1>

        const uint32_t sA = sbase + (uint32_t)buf * STG_STRIDE;
        const uint32_t sB = sA + 16384u;

        load_b_frags(b[0], sB, 0, lane, wn);

        #pragma unroll
        for (int kk = 0; kk < 4; ++kk) {
            const int cur = kk & 1;
            #pragma unroll
            for (int mt = 0; mt < 4; ++mt) {
                int r = wm * 64 + mt * 16 + (lane & 15);
                int c = kk * 2 + (lane >> 4);
                ldsm_x4(a[mt][0], a[mt][1], a[mt][2], a[mt][3],
                        sA + (uint32_t)(((r << 3) | (c ^ (r & 7))) << 4));
            }
            if (kk < 3) load_b_frags(b[cur ^ 1], sB, kk + 1, lane, wn);

            #pragma unroll
            for (int mt = 0; mt < 4; ++mt)
                #pragma unroll
                for (int nt = 0; nt < 4; ++nt)
                    mma16816(acc[mt][nt],
                             a[mt][0], a[mt][1], a[mt][2], a[mt][3],
                             b[cur][nt >> 1][(nt & 1) * 2],
                             b[cur][nt >> 1][(nt & 1) * 2 + 1]);
        }
    }

    // Epilogue: out = -s * sqrt(max(x2 + w2 - 2*cross, eps))
    const float sc = __ldg(scales);
    #pragma unroll
    for (int mt = 0; mt < 4; ++mt) {
        const int row = bm + wm * 64 + mt * 16 + (lane >> 2);
        const float x2a = g_x2[row];
        const float x2b = g_x2[row + 8];
        #pragma unroll
        for (int nt = 0; nt < 4; ++nt) {
            const int col = bn + wn * 32 + nt * 8 + ((lane & 3) << 1);
            if (col < N_DIM) {   // col even, N_DIM even -> col+1 also valid
                const float w2a = g_w2[col];
                const float w2b = g_w2[col + 1];
                float2 v;
                v.x = -sc * sqrtf(fmaxf(x2a + w2a - 2.f * acc[mt][nt][0], EPS_D2));
                v.y = -sc * sqrtf(fmaxf(x2a + w2b - 2.f * acc[mt][nt][1], EPS_D2));
                *reinterpret_cast<float2*>(out + (size_t)row * N_DIM + col) = v;
                v.x = -sc * sqrtf(fmaxf(x2b + w2a - 2.f * acc[mt][nt][2], EPS_D2));
                v.y = -sc * sqrtf(fmaxf(x2b + w2b - 2.f * acc[mt][nt][3], EPS_D2));
                *reinterpret_cast<float2*>(out + (size_t)(row + 8) * N_DIM + col) = v;
            }
        }
    }
}

// ---------------- launch ----------------
extern "C" void kernel_launch(void* const* d_in, const int* in_sizes, int n_in,
                              void* d_out, int out_size) {
    const float* x      = (const float*)d_in[0];  // [16384, 2048]
    const float* w      = (const float*)d_in[1];  // [1000, 2048]
    const float* scales = (const float*)d_in[2];  // [1]
    float* out          = (float*)d_out;          // [16384, 1000]

    cudaFuncSetAttribute(fused_kernel,
                         cudaFuncAttributeMaxDynamicSharedMemorySize,
                         NSTAGE * STG_STRIDE);

    reset_kernel<<<1, 32>>>();
    fused_kernel<<<NCONV + NGEMM, 256, NSTAGE * STG_STRIDE>>>(x, w, scales, out);
}